// round 9
// baseline (speedup 1.0000x reference)
#include <cuda_runtime.h>
#include <math.h>
#include <stdint.h>

#define BB 2
#define SS 2048
#define HH 32
#define DD 128
#define BSZ 16
#define NBLKS 512
#define NB (SS/BSZ)

#define ATTN_ELEMS (BB*SS*HH*DD)
#define CACHE_ELEMS (NBLKS*HH*DD*BSZ)

// ---------------- scratch ----------------------------------------------------
__device__ float g_cos[SS*DD];
__device__ float g_sin[SS*DD];
__device__ float g_qrot[ATTN_ELEMS];   // column-PERMUTED within 8-chunks
__device__ float g_krot[ATTN_ELEMS];   // column-PERMUTED within 8-chunks
__device__ int   g_tables[BB*NB];
__device__ int   g_inv[NBLKS];

// within-8 column permutation: logical o -> phys (o&3)*2 + (o>>2)
#define PERM8(d) (((d) & ~7) | ((((d)&3)<<1) | (((d)>>2)&1)))

// ---------------- block-table normalization + inverse map --------------------
__global__ void table_init_kernel(const void* __restrict__ t) {
    int tid = threadIdx.x;
    if (tid < NBLKS) g_inv[tid] = -1;
    __syncthreads();
    if (tid < BB*NB) {
        const int* t32 = (const int*)t;
        bool is64 = (t32[1] == 0 && t32[3] == 0);
        int val = is64 ? (int)((const long long*)t)[tid] : t32[tid];
        g_tables[tid] = val;
        if (val >= 0 && val < NBLKS) g_inv[val] = tid;
    }
}

// ---------------- RoPE table -------------------------------------------------
__global__ void rope_table_kernel() {
    int s = blockIdx.x;
    int d = threadIdx.x;
    double e = (double)d / 64.0;
    float inv_freq = (float)(1.0 / pow(10000.0, e));
    float freq = (float)s * inv_freq;
    double sd, cd;
    sincos((double)freq, &sd, &cd);
    float c = (float)cd, sn = (float)sd;
    g_cos[s*DD + d]      = c;
    g_cos[s*DD + d + 64] = c;
    g_sin[s*DD + d]      = sn;
    g_sin[s*DD + d + 64] = sn;
}

// ---------------- RoPE apply (writes permuted layout) ------------------------
__global__ void rope_kernel(const float* __restrict__ q,
                            const float* __restrict__ k) {
    int idx = blockIdx.x * blockDim.x + threadIdx.x;
    if (idx >= ATTN_ELEMS) return;
    int d   = idx & (DD-1);
    int bsh = idx >> 7;
    int s   = (bsh / HH) & (SS-1);
    float c  = g_cos[s*DD + d];
    float sn = g_sin[s*DD + d];
    int pidx   = (d < 64) ? idx + 64 : idx - 64;
    float sign = (d < 64) ? -1.0f : 1.0f;
    float qv = q[idx], qp = q[pidx];
    float kv = k[idx], kp = k[pidx];
    int widx = PERM8(idx);
    g_qrot[widx] = fmaf(sign*qp, sn, qv*c);
    g_krot[widx] = fmaf(sign*kp, sn, kv*c);
}

// ---------------- fused cache fill (copy-or-scatter) -------------------------
__global__ void cache_fill_kernel(const float* __restrict__ kc_in,
                                  const float* __restrict__ vc_in,
                                  const float* __restrict__ v,
                                  float* __restrict__ kc_out,
                                  float* __restrict__ vc_out) {
    int h   = blockIdx.x & (HH-1);
    int blk = blockIdx.x >> 5;
    int inv = g_inv[blk];
    size_t base = ((size_t)blk*HH + h) * (DD*BSZ);

    if (inv < 0) {
        const float4* ks = (const float4*)&kc_in[base];
        const float4* vs = (const float4*)&vc_in[base];
        float4* kd = (float4*)&kc_out[base];
        float4* vd = (float4*)&vc_out[base];
        for (int i = threadIdx.x; i < DD*BSZ/4; i += blockDim.x) {
            kd[i] = ks[i];
            vd[i] = vs[i];
        }
        return;
    }

    int b    = inv >> 7;
    int blkq = inv & (NB-1);

    __shared__ float sk[BSZ*129];
    __shared__ float sv[BSZ*129];

    for (int i = threadIdx.x; i < BSZ*DD; i += blockDim.x) {
        int p = i >> 7, d = i & (DD-1);
        int s = blkq*BSZ + p;
        size_t rowb = ((size_t)((b*SS + s)*HH + h))*DD;
        sk[p*129 + d] = g_krot[rowb + PERM8(d)];   // un-permute k
        sv[p*129 + d] = v[rowb + d];
    }
    __syncthreads();
    for (int i = threadIdx.x; i < BSZ*DD; i += blockDim.x) {
        int d = i >> 4, p = i & (BSZ-1);
        kc_out[base + (size_t)d*BSZ + p] = sk[p*129 + d];
        vc_out[base + (size_t)d*BSZ + p] = sv[p*129 + d];
    }
}

// ============================================================================
//   flash attention: tf32 mma (BM=128, BN=64, 8 warps), permuted QK layout,
//   K + Vt double-buffered, ONE barrier per tile.
// ============================================================================
#define KSTR 136                        /* row stride, floats (8 mod 32) */
#define KBYTES (64*KSTR*4)              /* 34816 */
#define VTSTR 136
#define VTBYTES (64*VTSTR*4)            /* 34816 */
#define ATTN_SMEM (2*KBYTES + 2*VTBYTES)/* 139264 */

static __device__ __forceinline__ uint32_t f2tf32(float x) {
    uint32_t r;
    asm("cvt.rna.tf32.f32 %0, %1;" : "=r"(r) : "f"(x));
    return r;
}

static __device__ __forceinline__ float exp2_fast(float y) {
    float t = y + 12582912.0f;
    int   n = __float_as_int(t) - 0x4B400000;
    float f = y - (t - 12582912.0f);
    float p = 0.0013333558f;
    p = fmaf(p, f, 0.0096181291f);
    p = fmaf(p, f, 0.055504109f);
    p = fmaf(p, f, 0.24022651f);
    p = fmaf(p, f, 0.69314718f);
    p = fmaf(p, f, 1.0f);
    return __int_as_float(__float_as_int(p) + (n << 23));
}

static __device__ __forceinline__ void cp16(uint32_t dst, const float* src) {
    asm volatile("cp.async.ca.shared.global [%0], [%1], 16;"
                 :: "r"(dst), "l"(src) : "memory");
}

#define MMA_TF32(D, A, B0, B1) \
    asm volatile("mma.sync.aligned.m16n8k8.row.col.f32.tf32.tf32.f32 " \
        "{%0,%1,%2,%3}, {%4,%5,%6,%7}, {%8,%9}, {%0,%1,%2,%3};" \
        : "+f"(D[0]), "+f"(D[1]), "+f"(D[2]), "+f"(D[3]) \
        : "r"(A[0]), "r"(A[1]), "r"(A[2]), "r"(A[3]), "r"(B0), "r"(B1))

static __device__ __forceinline__ void load_k_async(uint32_t sb_buf, int b,
                                                    int h, int k0, int tid) {
    #pragma unroll
    for (int it = 0; it < 8; it++) {
        int idx = it*256 + tid;
        int key = idx >> 5, c4 = idx & 31;
        const float* ks = &g_krot[((size_t)((b*SS + k0 + key)*HH + h))*DD + 4*c4];
        cp16(sb_buf + (uint32_t)key*(KSTR*4) + (uint32_t)c4*16, ks);
    }
    asm volatile("cp.async.commit_group;" ::: "memory");
}

__global__ void __launch_bounds__(256, 1)
attn_mma_kernel(const float* __restrict__ v, float* __restrict__ out) {
    extern __shared__ char sm[];
    uint32_t sb;
    asm("{ .reg .u64 t; cvta.to.shared.u64 t, %1; cvt.u32.u64 %0, t; }"
        : "=r"(sb) : "l"(sm));

    int tid  = threadIdx.x;
    int w    = tid >> 5;
    int lane = tid & 31;
    int gq   = lane >> 2;          // 0..7
    int j    = lane & 3;           // 0..3

    int bx = blockIdx.x;
    int qt = 15 - (bx & 15);       // reverse: heavy tiles first
    int bh = bx >> 4;
    int b  = bh >> 5;
    int h  = bh & (HH-1);
    int q0 = qt * 128;

    // ---- stage Q (tf32, permuted layout) in the K double-buffer region -----
    {
        uint32_t* Qs = (uint32_t*)sm;
        #pragma unroll
        for (int it = 0; it < 16; it++) {
            int idx = it*256 + tid;
            int row = idx >> 5, c4 = idx & 31;
            size_t src = ((size_t)((b*SS + q0 + row)*HH + h))*DD + 4*c4;
            float4 qv = *(const float4*)&g_qrot[src];
            uint4 qo = make_uint4(f2tf32(qv.x), f2tf32(qv.y),
                                  f2tf32(qv.z), f2tf32(qv.w));
            *(uint4*)&Qs[(uint32_t)row*KSTR + 4*c4] = qo;
        }
    }
    __syncthreads();

    // ---- Q A-fragments to registers (LDS.64 pairs: logical j & j+4) --------
    uint32_t qa[16][4];
    {
        const uint32_t* Qs = (const uint32_t*)sm;
        int r0 = 16*w + gq;
        #pragma unroll
        for (int kf = 0; kf < 16; kf++) {
            uint32_t base = (uint32_t)r0*KSTR + kf*8 + 2*j;
            uint2 lo = *(const uint2*)&Qs[base];
            uint2 hi = *(const uint2*)&Qs[base + 8*KSTR];
            qa[kf][0] = lo.x; qa[kf][2] = lo.y;
            qa[kf][1] = hi.x; qa[kf][3] = hi.y;
        }
    }
    __syncthreads();   // Q staging region free -> K double buffers

    float oacc[16][4];
    #pragma unroll
    for (int i = 0; i < 16; i++) {
        oacc[i][0] = 0.f; oacc[i][1] = 0.f; oacc[i][2] = 0.f; oacc[i][3] = 0.f;
    }
    float l0 = 0.f, l1 = 0.f;

    const float C = 0.12751743f;   // (1/sqrt(128)) * log2(e)
    int row0g = q0 + 16*w + gq;
    int row1g = row0g + 8;
    int ntiles = 2*qt + 2;

    // V geometry: thread handles keys 2kp,2kp+1, dims {it*32+dq .. +3}
    int kp = tid >> 3;             // 0..31
    int dq = (tid & 7) * 4;        // 0..28

    // ---- prologue: K(0) async; V(0) ldg+sts ---------------------------------
    load_k_async(sb, b, h, 0, tid);
    {
        uint32_t* Vt0 = (uint32_t*)(sm + 2*KBYTES);
        size_t rb0 = ((size_t)((b*SS + 2*kp)*HH + h))*DD;
        size_t rb1 = rb0 + (size_t)HH*DD;
        #pragma unroll
        for (int it = 0; it < 4; it++) {
            int d = it*32 + dq;
            uint4 a = *(const uint4*)&v[rb0 + d];
            uint4 bb = *(const uint4*)&v[rb1 + d];
            uint4 w0 = make_uint4(f2tf32(__uint_as_float(a.x)),
                                  f2tf32(__uint_as_float(a.y)),
                                  f2tf32(__uint_as_float(a.z)),
                                  f2tf32(__uint_as_float(a.w)));
            uint4 w1 = make_uint4(f2tf32(__uint_as_float(bb.x)),
                                  f2tf32(__uint_as_float(bb.y)),
                                  f2tf32(__uint_as_float(bb.z)),
                                  f2tf32(__uint_as_float(bb.w)));
            *(uint4*)&Vt0[(uint32_t)(2*kp)*VTSTR + d]     = w0;
            *(uint4*)&Vt0[(uint32_t)(2*kp + 1)*VTSTR + d] = w1;
        }
    }

    for (int t = 0; t < ntiles; t++) {
        asm volatile("cp.async.wait_group 0;" ::: "memory");
        __syncthreads();   // everyone's K(t) + Vt(t) ready; all done with t-1

        int k0 = t * 64;
        bool more = (t + 1 < ntiles);

        // K(t+1) prefetch (safe: all warps past sync => done reading this buf)
        if (more) load_k_async(sb + (uint32_t)((t+1)&1)*KBYTES, b, h, k0+64, tid);

        const uint32_t* Ku = (const uint32_t*)(sm + (uint32_t)(t&1)*KBYTES);
        const uint32_t* Vt = (const uint32_t*)(sm + 2*KBYTES
                                               + (uint32_t)(t&1)*VTBYTES);
        uint32_t* Vtn = (uint32_t*)(sm + 2*KBYTES + (uint32_t)((t+1)&1)*VTBYTES);

        // ---- V(t+1) global loads (hidden under QK MMA) ---------------------
        uint4 va[4], vb4[4];
        if (more) {
            size_t rb0 = ((size_t)((b*SS + k0 + 64 + 2*kp)*HH + h))*DD;
            size_t rb1 = rb0 + (size_t)HH*DD;
            #pragma unroll
            for (int it = 0; it < 4; it++) {
                int d = it*32 + dq;
                va[it]  = *(const uint4*)&v[rb0 + d];
                vb4[it] = *(const uint4*)&v[rb1 + d];
            }
        }

        // ---- QK^T : S[16 x 64] per warp (tf32, LDS.64 B-frags) -------------
        float sacc[8][4];
        #pragma unroll
        for (int nf = 0; nf < 8; nf++) {
            sacc[nf][0] = 0.f; sacc[nf][1] = 0.f;
            sacc[nf][2] = 0.f; sacc[nf][3] = 0.f;
        }
        #pragma unroll
        for (int nf = 0; nf < 8; nf++) {
            uint32_t kb = (uint32_t)(nf*8 + gq)*KSTR + 2*j;
            #pragma unroll
            for (int kf = 0; kf < 16; kf++) {
                uint2 bb = *(const uint2*)&Ku[kb + kf*8];
                MMA_TF32(sacc[nf], qa[kf], bb.x, bb.y);
            }
        }

        // ---- store V(t+1) (rna tf32) into next Vt buffer -------------------
        if (more) {
            #pragma unroll
            for (int it = 0; it < 4; it++) {
                int d = it*32 + dq;
                uint4 w0 = make_uint4(f2tf32(__uint_as_float(va[it].x)),
                                      f2tf32(__uint_as_float(va[it].y)),
                                      f2tf32(__uint_as_float(va[it].z)),
                                      f2tf32(__uint_as_float(va[it].w)));
                uint4 w1 = make_uint4(f2tf32(__uint_as_float(vb4[it].x)),
                                      f2tf32(__uint_as_float(vb4[it].y)),
                                      f2tf32(__uint_as_float(vb4[it].z)),
                                      f2tf32(__uint_as_float(vb4[it].w)));
                *(uint4*)&Vtn[(uint32_t)(2*kp)*VTSTR + d]     = w0;
                *(uint4*)&Vtn[(uint32_t)(2*kp + 1)*VTSTR + d] = w1;
            }
        }

        // ---- softmax (unnormalized) + remap D-frag -> A-frag ---------------
        bool maskt = (t >= 2*qt);
        uint32_t pa[8][4];
        int src0 = (lane & ~3) | (j >> 1);
        int src2 = src0 + 2;
        bool odd = (j & 1);
        #pragma unroll
        for (int nf = 0; nf < 8; nf++) {
            int c = k0 + 8*nf + 2*j;
            float p0 = exp2_fast(sacc[nf][0] * C);
            float p1 = exp2_fast(sacc[nf][1] * C);
            float p2 = exp2_fast(sacc[nf][2] * C);
            float p3 = exp2_fast(sacc[nf][3] * C);
            if (maskt) {
                if (c     > row0g) p0 = 0.f;
                if (c + 1 > row0g) p1 = 0.f;
                if (c     > row1g) p2 = 0.f;
                if (c + 1 > row1g) p3 = 0.f;
            }
            uint32_t t0 = f2tf32(p0), t1 = f2tf32(p1);
            uint32_t t2 = f2tf32(p2), t3 = f2tf32(p3);
            l0 += __uint_as_float(t0) + __uint_as_float(t1);
            l1 += __uint_as_float(t2) + __uint_as_float(t3);
            uint32_t x0 = __shfl_sync(0xffffffffu, t0, src0);
            uint32_t x1 = __shfl_sync(0xffffffffu, t1, src0);
            uint32_t y0 = __shfl_sync(0xffffffffu, t2, src0);
            uint32_t y1 = __shfl_sync(0xffffffffu, t3, src0);
            uint32_t z0 = __shfl_sync(0xffffffffu, t0, src2);
            uint32_t z1 = __shfl_sync(0xffffffffu, t1, src2);
            uint32_t w0 = __shfl_sync(0xffffffffu, t2, src2);
            uint32_t w1 = __shfl_sync(0xffffffffu, t3, src2);
            pa[nf][0] = odd ? x1 : x0;
            pa[nf][1] = odd ? y1 : y0;
            pa[nf][2] = odd ? z1 : z0;
            pa[nf][3] = odd ? w1 : w0;
        }

        // ---- P·V : O[16 x 128] += P[16 x 64] V[64 x 128] (tf32) ------------
        // Vt(t) was fully written during t-1 and certified at this tile's sync.
        #pragma unroll
        for (int nf = 0; nf < 16; nf++) {
            uint32_t vbs = (uint32_t)j*VTSTR + nf*8 + gq;
            #pragma unroll
            for (int kf = 0; kf < 8; kf++) {
                uint32_t b0 = Vt[vbs + (uint32_t)(kf*8)*VTSTR];
                uint32_t b1 = Vt[vbs + (uint32_t)(kf*8 + 4)*VTSTR];
                MMA_TF32(oacc[nf], pa[kf], b0, b1);
            }
        }
    }

    // ---- epilogue ----------------------------------------------------------
    l0 += __shfl_xor_sync(0xffffffffu, l0, 1);
    l0 += __shfl_xor_sync(0xffffffffu, l0, 2);
    l1 += __shfl_xor_sync(0xffffffffu, l1, 1);
    l1 += __shfl_xor_sync(0xffffffffu, l1, 2);
    float inv0 = 1.0f / l0, inv1 = 1.0f / l1;

    size_t base0 = ((size_t)(b*SS + row0g)*HH + h)*DD;
    size_t base1 = ((size_t)(b*SS + row1g)*HH + h)*DD;
    #pragma unroll
    for (int nf = 0; nf < 16; nf++) {
        int col = 8*nf + 2*j;
        float2 o0 = make_float2(oacc[nf][0]*inv0, oacc[nf][1]*inv0);
        float2 o1 = make_float2(oacc[nf][2]*inv1, oacc[nf][3]*inv1);
        *(float2*)&out[base0 + col] = o0;
        *(float2*)&out[base1 + col] = o1;
    }
}

// ---------------- launcher ----------------------------------------------------
extern "C" void kernel_launch(void* const* d_in, const int* in_sizes, int n_in,
                              void* d_out, int out_size) {
    const float* q  = (const float*)d_in[0];
    const float* k  = (const float*)d_in[1];
    const float* v  = (const float*)d_in[2];
    const float* kc = (const float*)d_in[3];
    const float* vc = (const float*)d_in[4];
    const void*  tables = d_in[6];
    float* out = (float*)d_out;

    bool do_cache = (out_size >= ATTN_ELEMS + 2*CACHE_ELEMS);
    float* kc_out = out + ATTN_ELEMS;
    float* vc_out = kc_out + CACHE_ELEMS;

    cudaFuncSetAttribute(attn_mma_kernel,
                         cudaFuncAttributeMaxDynamicSharedMemorySize, ATTN_SMEM);

    table_init_kernel<<<1, 512>>>(tables);
    rope_table_kernel<<<SS, 64>>>();
    rope_kernel<<<(ATTN_ELEMS + 255)/256, 256>>>(q, k);
    if (do_cache)
        cache_fill_kernel<<<NBLKS*HH, 128>>>(kc, vc, v, kc_out, vc_out);
    attn_mma_kernel<<<BB*HH*(SS/128), 256, ATTN_SMEM>>>(v, out);
}

// round 10
// speedup vs baseline: 1.2820x; 1.2820x over previous
#include <cuda_runtime.h>
#include <cuda_fp16.h>
#include <math.h>
#include <stdint.h>

#define BB 2
#define SS 2048
#define HH 32
#define DD 128
#define BSZ 16
#define NBLKS 512
#define NB (SS/BSZ)

#define ATTN_ELEMS (BB*SS*HH*DD)
#define CACHE_ELEMS (NBLKS*HH*DD*BSZ)

// ---------------- scratch ----------------------------------------------------
__device__ float    g_cos[SS*DD];
__device__ float    g_sin[SS*DD];
__device__ float    g_krot[ATTN_ELEMS];      // plain layout (for cache fill)
__device__ uint32_t g_q16[ATTN_ELEMS/2];     // f16x2, word-permuted for B/A frags
__device__ uint32_t g_k16[ATTN_ELEMS/2];
__device__ int      g_tables[BB*NB];
__device__ int      g_inv[NBLKS];

// word-permutation within 8-word chunks: logical w -> (w&3)*2 + (w>>2)
#define PW(m) (((m) & ~7) | ((((m)&3)<<1) | (((m)>>2)&1)))

static __device__ __forceinline__ uint32_t packf16(float hi, float lo) {
    uint32_t r;
    asm("cvt.rn.f16x2.f32 %0, %1, %2;" : "=r"(r) : "f"(hi), "f"(lo));
    return r;
}

// ---------------- block-table normalization + inverse map --------------------
__global__ void table_init_kernel(const void* __restrict__ t) {
    int tid = threadIdx.x;
    if (tid < NBLKS) g_inv[tid] = -1;
    __syncthreads();
    if (tid < BB*NB) {
        const int* t32 = (const int*)t;
        bool is64 = (t32[1] == 0 && t32[3] == 0);
        int val = is64 ? (int)((const long long*)t)[tid] : t32[tid];
        g_tables[tid] = val;
        if (val >= 0 && val < NBLKS) g_inv[val] = tid;
    }
}

// ---------------- RoPE table -------------------------------------------------
__global__ void rope_table_kernel() {
    int s = blockIdx.x;
    int d = threadIdx.x;
    double e = (double)d / 64.0;
    float inv_freq = (float)(1.0 / pow(10000.0, e));
    float freq = (float)s * inv_freq;
    double sd, cd;
    sincos((double)freq, &sd, &cd);
    float c = (float)cd, sn = (float)sd;
    g_cos[s*DD + d]      = c;
    g_cos[s*DD + d + 64] = c;
    g_sin[s*DD + d]      = sn;
    g_sin[s*DD + d + 64] = sn;
}

// ---------------- RoPE apply: writes f32 K (plain) + f16x2 Q/K (permuted) ----
__global__ void rope_kernel(const float* __restrict__ q,
                            const float* __restrict__ k) {
    int i2 = blockIdx.x * blockDim.x + threadIdx.x;     // d-pair index
    if (i2 >= ATTN_ELEMS/2) return;
    int d2  = i2 & 63;
    int row = i2 >> 6;              // (b*S+s)*H + h
    int s   = (row / HH) & (SS-1);
    int d   = 2*d2;
    size_t base = (size_t)row * DD;
    int   doff = (d < 64) ? 64 : -64;
    float sign = (d < 64) ? -1.0f : 1.0f;
    float c0 = g_cos[s*DD+d],   c1 = g_cos[s*DD+d+1];
    float s0 = g_sin[s*DD+d],   s1 = g_sin[s*DD+d+1];
    float q0 = q[base+d],       q1 = q[base+d+1];
    float qp0 = q[base+d+doff], qp1 = q[base+d+doff+1];
    float k0 = k[base+d],       k1 = k[base+d+1];
    float kp0 = k[base+d+doff], kp1 = k[base+d+doff+1];
    float qr0 = fmaf(sign*qp0, s0, q0*c0);
    float qr1 = fmaf(sign*qp1, s1, q1*c1);
    float kr0 = fmaf(sign*kp0, s0, k0*c0);
    float kr1 = fmaf(sign*kp1, s1, k1*c1);
    g_krot[base+d]   = kr0;
    g_krot[base+d+1] = kr1;
    size_t wpos = (size_t)row*64 + PW(d2);
    g_q16[wpos] = packf16(qr1, qr0);
    g_k16[wpos] = packf16(kr1, kr0);
}

// ---------------- fused cache fill (copy-or-scatter) -------------------------
__global__ void cache_fill_kernel(const float* __restrict__ kc_in,
                                  const float* __restrict__ vc_in,
                                  const float* __restrict__ v,
                                  float* __restrict__ kc_out,
                                  float* __restrict__ vc_out) {
    int h   = blockIdx.x & (HH-1);
    int blk = blockIdx.x >> 5;
    int inv = g_inv[blk];
    size_t base = ((size_t)blk*HH + h) * (DD*BSZ);

    if (inv < 0) {
        const float4* ks = (const float4*)&kc_in[base];
        const float4* vs = (const float4*)&vc_in[base];
        float4* kd = (float4*)&kc_out[base];
        float4* vd = (float4*)&vc_out[base];
        for (int i = threadIdx.x; i < DD*BSZ/4; i += blockDim.x) {
            kd[i] = ks[i];
            vd[i] = vs[i];
        }
        return;
    }

    int b    = inv >> 7;
    int blkq = inv & (NB-1);

    __shared__ float sk[BSZ*129];
    __shared__ float sv[BSZ*129];

    for (int i = threadIdx.x; i < BSZ*DD; i += blockDim.x) {
        int p = i >> 7, d = i & (DD-1);
        int s = blkq*BSZ + p;
        size_t rowb = ((size_t)((b*SS + s)*HH + h))*DD;
        sk[p*129 + d] = g_krot[rowb + d];
        sv[p*129 + d] = v[rowb + d];
    }
    __syncthreads();
    for (int i = threadIdx.x; i < BSZ*DD; i += blockDim.x) {
        int d = i >> 4, p = i & (BSZ-1);
        kc_out[base + (size_t)d*BSZ + p] = sk[p*129 + d];
        vc_out[base + (size_t)d*BSZ + p] = sv[p*129 + d];
    }
}

// ============================================================================
//   flash attention: fp16 mma m16n8k16 (BM=128, BN=64, 8 warps), f32 accum
// ============================================================================
#define KROW 68                          /* words per K/Q row (4 mod 32 banks) */
#define KBYTES (64*KROW*4)               /* 17408 per K buffer */
#define VSTRW 38                         /* Vt row stride (words), even        */
#define VTBYTES (128*VSTRW*4)            /* 19456 */
#define ATTN_SMEM (2*KBYTES + VTBYTES)   /* 54272 */

static __device__ __forceinline__ float exp2_fast(float y) {
    float t = y + 12582912.0f;
    int   n = __float_as_int(t) - 0x4B400000;
    float f = y - (t - 12582912.0f);
    float p = 0.0013333558f;
    p = fmaf(p, f, 0.0096181291f);
    p = fmaf(p, f, 0.055504109f);
    p = fmaf(p, f, 0.24022651f);
    p = fmaf(p, f, 0.69314718f);
    p = fmaf(p, f, 1.0f);
    return __int_as_float(__float_as_int(p) + (n << 23));
}

static __device__ __forceinline__ void cp16(uint32_t dst, const void* src) {
    asm volatile("cp.async.ca.shared.global [%0], [%1], 16;"
                 :: "r"(dst), "l"(src) : "memory");
}

#define MMA_F16(D, A, B0, B1) \
    asm volatile("mma.sync.aligned.m16n8k16.row.col.f32.f16.f16.f32 " \
        "{%0,%1,%2,%3}, {%4,%5,%6,%7}, {%8,%9}, {%0,%1,%2,%3};" \
        : "+f"(D[0]), "+f"(D[1]), "+f"(D[2]), "+f"(D[3]) \
        : "r"(A[0]), "r"(A[1]), "r"(A[2]), "r"(A[3]), "r"(B0), "r"(B1))

static __device__ __forceinline__ void load_k_async(uint32_t sb_buf, int b,
                                                    int h, int k0, int tid) {
    #pragma unroll
    for (int it = 0; it < 4; it++) {
        int idx = it*256 + tid;
        int key = idx >> 4, c4 = idx & 15;       // 16 chunks of 16B per row
        const uint32_t* ks = &g_k16[((size_t)((b*SS + k0 + key)*HH + h))*64 + c4*4];
        cp16(sb_buf + (uint32_t)key*(KROW*4) + (uint32_t)c4*16, ks);
    }
    asm volatile("cp.async.commit_group;" ::: "memory");
}

__global__ void __launch_bounds__(256, 1)
attn_mma_kernel(const float* __restrict__ v, float* __restrict__ out) {
    extern __shared__ char sm[];
    uint32_t sb;
    asm("{ .reg .u64 t; cvta.to.shared.u64 t, %1; cvt.u32.u64 %0, t; }"
        : "=r"(sb) : "l"(sm));

    int tid  = threadIdx.x;
    int w    = tid >> 5;
    int lane = tid & 31;
    int gq   = lane >> 2;          // 0..7
    int j    = lane & 3;           // 0..3

    int bx = blockIdx.x;
    int qt = 15 - (bx & 15);       // reverse: heavy tiles first
    int bh = bx >> 4;
    int b  = bh >> 5;
    int h  = bh & (HH-1);
    int q0 = qt * 128;

    // ---- stage Q (f16, permuted words) into the K double-buffer region -----
    #pragma unroll
    for (int it = 0; it < 8; it++) {
        int idx = it*256 + tid;
        int row = idx >> 4, c4 = idx & 15;
        const uint32_t* qs = &g_q16[((size_t)((b*SS + q0 + row)*HH + h))*64 + c4*4];
        cp16(sb + (uint32_t)row*(KROW*4) + (uint32_t)c4*16, qs);
    }
    asm volatile("cp.async.commit_group;" ::: "memory");
    asm volatile("cp.async.wait_group 0;" ::: "memory");
    __syncthreads();

    // ---- Q A-fragments to registers (LDS.64: words {j, j+4} adjacent) ------
    uint32_t qa[8][4];
    {
        const uint32_t* Qs = (const uint32_t*)sm;
        int r0 = 16*w + gq;
        #pragma unroll
        for (int kf = 0; kf < 8; kf++) {
            uint32_t base = (uint32_t)r0*KROW + kf*8 + 2*j;
            uint2 lo = *(const uint2*)&Qs[base];             // (a0, a2)
            uint2 hi = *(const uint2*)&Qs[base + 8*KROW];    // (a1, a3)
            qa[kf][0] = lo.x; qa[kf][2] = lo.y;
            qa[kf][1] = hi.x; qa[kf][3] = hi.y;
        }
    }
    __syncthreads();   // Q staging region free -> K double buffers

    float oacc[16][4];
    #pragma unroll
    for (int i = 0; i < 16; i++) {
        oacc[i][0] = 0.f; oacc[i][1] = 0.f; oacc[i][2] = 0.f; oacc[i][3] = 0.f;
    }
    float l0 = 0.f, l1 = 0.f;

    const float C = 0.12751743f;   // (1/sqrt(128)) * log2(e)
    int row0g = q0 + 16*w + gq;
    int row1g = row0g + 8;
    int ntiles = 2*qt + 2;

    // V geometry: thread handles key-pair kp (keys 2kp,2kp+1), dims dq..+3 x4
    int kp = tid >> 3;             // 0..31
    int dq = (tid & 7) * 4;        // 0..28
    uint32_t kpw = PW(kp);         // permuted word slot within Vt row

    load_k_async(sb, b, h, 0, tid);

    for (int t = 0; t < ntiles; t++) {
        if (t + 1 < ntiles) {
            load_k_async(sb + (uint32_t)((t+1)&1)*KBYTES, b, h, (t+1)*64, tid);
            asm volatile("cp.async.wait_group 1;" ::: "memory");
        } else {
            asm volatile("cp.async.wait_group 0;" ::: "memory");
        }
        __syncthreads();   // K(t) ready; PV(t-1) done so Vt writable

        int k0 = t * 64;
        const uint32_t* Ku = (const uint32_t*)(sm + (uint32_t)(t&1)*KBYTES);
        uint32_t*       Vt = (uint32_t*)(sm + 2*KBYTES);

        // ---- V global loads (hidden under QK MMA) --------------------------
        uint4 va[4], vb4[4];
        {
            size_t rb0 = ((size_t)((b*SS + k0 + 2*kp)*HH + h))*DD;
            size_t rb1 = rb0 + (size_t)HH*DD;
            #pragma unroll
            for (int it = 0; it < 4; it++) {
                int d = it*32 + dq;
                va[it]  = *(const uint4*)&v[rb0 + d];
                vb4[it] = *(const uint4*)&v[rb1 + d];
            }
        }

        // ---- QK^T : S[16 x 64] per warp (fp16 k16) -------------------------
        float sacc[8][4];
        #pragma unroll
        for (int nf = 0; nf < 8; nf++) {
            sacc[nf][0] = 0.f; sacc[nf][1] = 0.f;
            sacc[nf][2] = 0.f; sacc[nf][3] = 0.f;
        }
        #pragma unroll
        for (int nf = 0; nf < 8; nf++) {
            uint32_t kb = (uint32_t)(nf*8 + gq)*KROW + 2*j;
            #pragma unroll
            for (int kf = 0; kf < 8; kf++) {
                uint2 bb = *(const uint2*)&Ku[kb + kf*8];
                MMA_F16(sacc[nf], qa[kf], bb.x, bb.y);
            }
        }

        // ---- pack V -> f16x2 key-pairs: Vt[d][kp] = {lo=v[2kp], hi=v[2kp+1]}
        #pragma unroll
        for (int it = 0; it < 4; it++) {
            int d = it*32 + dq;
            Vt[(uint32_t)(d+0)*VSTRW + kpw] =
                packf16(__uint_as_float(vb4[it].x), __uint_as_float(va[it].x));
            Vt[(uint32_t)(d+1)*VSTRW + kpw] =
                packf16(__uint_as_float(vb4[it].y), __uint_as_float(va[it].y));
            Vt[(uint32_t)(d+2)*VSTRW + kpw] =
                packf16(__uint_as_float(vb4[it].z), __uint_as_float(va[it].z));
            Vt[(uint32_t)(d+3)*VSTRW + kpw] =
                packf16(__uint_as_float(vb4[it].w), __uint_as_float(va[it].w));
        }

        // ---- softmax (unnormalized) -> fp16 A-fragments (identity remap) ---
        bool maskt = (t >= 2*qt);
        uint32_t pa[4][4];
        #pragma unroll
        for (int nf = 0; nf < 8; nf++) {
            int c = k0 + 8*nf + 2*j;
            float p0 = exp2_fast(sacc[nf][0] * C);
            float p1 = exp2_fast(sacc[nf][1] * C);
            float p2 = exp2_fast(sacc[nf][2] * C);
            float p3 = exp2_fast(sacc[nf][3] * C);
            if (maskt) {
                if (c     > row0g) p0 = 0.f;
                if (c + 1 > row0g) p1 = 0.f;
                if (c     > row1g) p2 = 0.f;
                if (c + 1 > row1g) p3 = 0.f;
            }
            uint32_t w01 = packf16(p1, p0);
            uint32_t w23 = packf16(p3, p2);
            // accumulate l from ROUNDED weights (numerator consistency)
            float2 f01 = __half22float2(*reinterpret_cast<__half2*>(&w01));
            float2 f23 = __half22float2(*reinterpret_cast<__half2*>(&w23));
            l0 += f01.x + f01.y;
            l1 += f23.x + f23.y;
            pa[nf>>1][(nf&1)*2 + 0] = w01;   // a0 (nf even) / a2 (nf odd)
            pa[nf>>1][(nf&1)*2 + 1] = w23;   // a1 (nf even) / a3 (nf odd)
        }
        __syncthreads();   // Vt visible to all warps

        // ---- P·V : O[16 x 128] += P[16 x 64] V[64 x 128] (fp16 k16) --------
        #pragma unroll
        for (int nf = 0; nf < 16; nf++) {
            uint32_t vbs = (uint32_t)(nf*8 + gq)*VSTRW + 2*j;
            #pragma unroll
            for (int kf = 0; kf < 4; kf++) {
                uint2 bb = *(const uint2*)&Vt[vbs + kf*8];
                MMA_F16(oacc[nf], pa[kf], bb.x, bb.y);
            }
        }
        // loop-top __syncthreads protects Vt and the K buffer being refilled
    }

    // ---- epilogue ----------------------------------------------------------
    l0 += __shfl_xor_sync(0xffffffffu, l0, 1);
    l0 += __shfl_xor_sync(0xffffffffu, l0, 2);
    l1 += __shfl_xor_sync(0xffffffffu, l1, 1);
    l1 += __shfl_xor_sync(0xffffffffu, l1, 2);
    float inv0 = 1.0f / l0, inv1 = 1.0f / l1;

    size_t base0 = ((size_t)(b*SS + row0g)*HH + h)*DD;
    size_t base1 = ((size_t)(b*SS + row1g)*HH + h)*DD;
    #pragma unroll
    for (int nf = 0; nf < 16; nf++) {
        int col = 8*nf + 2*j;
        float2 o0 = make_float2(oacc[nf][0]*inv0, oacc[nf][1]*inv0);
        float2 o1 = make_float2(oacc[nf][2]*inv1, oacc[nf][3]*inv1);
        *(float2*)&out[base0 + col] = o0;
        *(float2*)&out[base1 + col] = o1;
    }
}

// ---------------- launcher ----------------------------------------------------
extern "C" void kernel_launch(void* const* d_in, const int* in_sizes, int n_in,
                              void* d_out, int out_size) {
    const float* q  = (const float*)d_in[0];
    const float* k  = (const float*)d_in[1];
    const float* v  = (const float*)d_in[2];
    const float* kc = (const float*)d_in[3];
    const float* vc = (const float*)d_in[4];
    const void*  tables = d_in[6];
    float* out = (float*)d_out;

    bool do_cache = (out_size >= ATTN_ELEMS + 2*CACHE_ELEMS);
    float* kc_out = out + ATTN_ELEMS;
    float* vc_out = kc_out + CACHE_ELEMS;

    cudaFuncSetAttribute(attn_mma_kernel,
                         cudaFuncAttributeMaxDynamicSharedMemorySize, ATTN_SMEM);

    table_init_kernel<<<1, 512>>>(tables);
    rope_table_kernel<<<SS, 64>>>();
    rope_kernel<<<(ATTN_ELEMS/2 + 255)/256, 256>>>(q, k);
    if (do_cache)
        cache_fill_kernel<<<NBLKS*HH, 128>>>(kc, vc, v, kc_out, vc_out);
    attn_mma_kernel<<<BB*HH*(SS/128), 256, ATTN_SMEM>>>(v, out);
}